// round 10
// baseline (speedup 1.0000x reference)
#include <cuda_runtime.h>
#include <cuda_fp16.h>
#include <mma.h>
#include <stdint.h>

using namespace nvcuda;

#define MAXN 100000
#define NPAD (MAXN + 64)
#define MAXE 1600000
#define IN_DIM 128
#define HC 128
#define OUT_DIM 32
#define HEADS 4
#define NEG_SLOPE 0.2f
#define EPS 1e-16f

#define LDA 136                       // half elems per A row (128+8)
#define LDB1 136
#define LDB2 40
#define GEMM1_SMEM (64*LDA*2 + 128*LDB1*2)   // 52224 B (>= 32KB fp32 out stage)
#define GEMM2_SMEM (64*LDA*2 + 128*LDB2*2)   // 27648 B (>= 8KB out stage)

// ---------------- scratch (device globals; zero-init at load) ----------------
__device__ __half g_h1h[NPAD * HC];
__device__ float  g_agg1[NPAD * HC];
__device__ __half g_h2h[NPAD * OUT_DIM];
__device__ float g_asrc1[MAXN * HEADS];
__device__ float g_adst1[MAXN * HEADS];
__device__ float g_asrc2[MAXN];
__device__ float g_adst2[MAXN];
// CSR scratch (deg/cursor self-healing; btot[NB..127] stays 0 from load)
__device__ int g_deg[MAXN];
__device__ int g_rowptr[MAXN + 1];
__device__ int g_rowfin[MAXN];
__device__ int g_cursor[MAXN];
__device__ int g_esrc[MAXE + MAXN];
__device__ int g_btot[128];

// ---------------- #1: histogram -----------------------------------------------
__global__ void hist_kernel(const int* __restrict__ dst, int E, int EN) {
    int t = blockIdx.x * blockDim.x + threadIdx.x;
    if (t >= EN) return;
    int d = (t < E) ? dst[t] : (t - E);
    atomicAdd(&g_deg[d], 1);
}

// ---------------- #2: per-block scan ------------------------------------------
__global__ void scan1_kernel(int N) {
    __shared__ int sh[1024];
    int i = blockIdx.x * 1024 + threadIdx.x;
    int v = (i < N) ? g_deg[i] : 0;
    if (i < N) g_deg[i] = 0;            // self-heal
    sh[threadIdx.x] = v;
    __syncthreads();
#pragma unroll
    for (int off = 1; off < 1024; off <<= 1) {
        int t = (threadIdx.x >= off) ? sh[threadIdx.x - off] : 0;
        __syncthreads();
        sh[threadIdx.x] += t;
        __syncthreads();
    }
    if (i < N) g_rowptr[i] = sh[threadIdx.x] - v;
    if (threadIdx.x == 1023) g_btot[blockIdx.x] = sh[1023];
}

// ---------------- #3: scatter (inline btot scan, writes rowfin) ---------------
__global__ void scatter_kernel(const int* __restrict__ src,
                               const int* __restrict__ dst, int E, int EN) {
    __shared__ int boff[128];
    if (threadIdx.x < 128) boff[threadIdx.x] = g_btot[threadIdx.x];
    __syncthreads();
    if (threadIdx.x < 128) {
        int v = boff[threadIdx.x];
        int acc = v;
#pragma unroll
        for (int off = 1; off < 128; off <<= 1) {
            int u = (threadIdx.x >= off) ? boff[threadIdx.x - off] : 0;
            __syncthreads();
            boff[threadIdx.x] = acc = acc + u;
            __syncthreads();
        }
        boff[threadIdx.x] = acc - v;
    } else {
#pragma unroll
        for (int off = 1; off < 128; off <<= 1) { __syncthreads(); __syncthreads(); }
    }
    __syncthreads();

    int t = blockIdx.x * blockDim.x + threadIdx.x;
    if (t >= EN) return;
    int s, d;
    if (t < E) { s = src[t]; d = dst[t]; }
    else       { s = t - E;  d = s; }
    int base = g_rowptr[d] + boff[d >> 10];
    g_rowfin[d] = base;
    int pos = base + atomicAdd(&g_cursor[d], 1);
    g_esrc[pos] = s;
}

// ---------------- #4: GEMM1 (plain fp16 WMMA) + fused attn1 -------------------
__global__ void gemm1_kernel(const float* __restrict__ x,
                             const float* __restrict__ W,
                             const float* __restrict__ att_s,
                             const float* __restrict__ att_d, int N) {
    extern __shared__ __half smh[];
    __half* As = smh;                   // 64 x LDA
    __half* Bs = smh + 64 * LDA;        // 128 x LDB1
    float* outs = (float*)smh;          // reused after MMA: 64*128 fp32 = 32KB
    int tid = threadIdx.x;
    int row0 = blockIdx.x * 64;

    // stage W as fp16 (128x128: 4096 float4 -> uint2)
    {
        uint2* db = (uint2*)Bs;
        const float4* sw = (const float4*)W;
        for (int i = tid; i < 4096; i += 256) {
            int r = i >> 5, c4 = i & 31;
            float4 f = sw[i];
            uint2 p;
            half2 h0 = __floats2half2_rn(f.x, f.y);
            half2 h1 = __floats2half2_rn(f.z, f.w);
            p.x = *(uint32_t*)&h0;
            p.y = *(uint32_t*)&h1;
            db[r * 34 + c4] = p;
        }
    }
    // stage x tile as fp16 (64x128: 2048 float4)
    {
        uint2* da = (uint2*)As;
        const float4* sx = (const float4*)x;
        for (int i = tid; i < 2048; i += 256) {
            int r = i >> 5, c4 = i & 31;
            int g = row0 + r;
            float4 f = (g < N) ? sx[(size_t)g * 32 + c4]
                               : make_float4(0.f, 0.f, 0.f, 0.f);
            uint2 p;
            half2 h0 = __floats2half2_rn(f.x, f.y);
            half2 h1 = __floats2half2_rn(f.z, f.w);
            p.x = *(uint32_t*)&h0;
            p.y = *(uint32_t*)&h1;
            da[r * 34 + c4] = p;
        }
    }
    __syncthreads();

    int w = tid >> 5;
    int lane = tid & 31;
    int wr = w >> 1, wc = w & 1;        // warp tile: rows wr*16, cols wc*64
    wmma::fragment<wmma::accumulator, 16, 16, 16, float> acc[4];
#pragma unroll
    for (int i = 0; i < 4; i++) wmma::fill_fragment(acc[i], 0.f);

#pragma unroll
    for (int k = 0; k < 8; k++) {
        wmma::fragment<wmma::matrix_a, 16, 16, 16, __half, wmma::row_major> a;
        wmma::load_matrix_sync(a, As + (wr * 16) * LDA + k * 16, LDA);
#pragma unroll
        for (int ct = 0; ct < 4; ct++) {
            wmma::fragment<wmma::matrix_b, 16, 16, 16, __half, wmma::row_major> b;
            wmma::load_matrix_sync(b, Bs + (k * 16) * LDB1 + wc * 64 + ct * 16, LDB1);
            wmma::mma_sync(acc[ct], a, b, acc[ct]);
        }
    }

    __syncthreads();
#pragma unroll
    for (int ct = 0; ct < 4; ct++)
        wmma::store_matrix_sync(outs + (wr * 16) * 128 + wc * 64 + ct * 16,
                                acc[ct], 128, wmma::mem_row_major);
    __syncthreads();

    // fp16 global store
    for (int i = tid; i < 64 * 64; i += 256) {
        int r = i >> 6, c2 = i & 63;
        int g = row0 + r;
        if (g < N) {
            float2 f = ((const float2*)outs)[r * 64 + c2];
            ((half2*)g_h1h)[(size_t)g * 64 + c2] = __floats2half2_rn(f.x, f.y);
        }
    }

    // fused attn1: warp w handles rows w*8 .. w*8+7
    float4 as = ((const float4*)att_s)[lane];
    float4 ad = ((const float4*)att_d)[lane];
#pragma unroll
    for (int r8 = 0; r8 < 8; r8++) {
        int r = w * 8 + r8;
        int g = row0 + r;
        float4 hv = ((const float4*)outs)[r * 32 + lane];
        float ps = hv.x * as.x + hv.y * as.y + hv.z * as.z + hv.w * as.w;
        float pd = hv.x * ad.x + hv.y * ad.y + hv.z * ad.z + hv.w * ad.w;
        ps += __shfl_xor_sync(0xFFFFFFFFu, ps, 1);
        pd += __shfl_xor_sync(0xFFFFFFFFu, pd, 1);
        ps += __shfl_xor_sync(0xFFFFFFFFu, ps, 2);
        pd += __shfl_xor_sync(0xFFFFFFFFu, pd, 2);
        ps += __shfl_xor_sync(0xFFFFFFFFu, ps, 4);
        pd += __shfl_xor_sync(0xFFFFFFFFu, pd, 4);
        if ((lane & 7) == 0 && g < N) {
            int h = lane >> 3;
            g_asrc1[g * 4 + h] = ps;
            g_adst1[g * 4 + h] = pd;
        }
    }
}

// ---------------- #6: GEMM2 (plain fp16 WMMA) + fused attn2 -------------------
__global__ void gemm2_kernel(const float* __restrict__ W,
                             const float* __restrict__ att_s,
                             const float* __restrict__ att_d, int N) {
    extern __shared__ __half smh[];
    __half* As = smh;                   // 64 x LDA
    __half* Bs = smh + 64 * LDA;        // 128 x LDB2
    float* outs = (float*)smh;          // reused: 64*32 fp32 = 8KB
    int tid = threadIdx.x;
    int lane = tid & 31;
    int row0 = blockIdx.x * 64;

    // stage W2 (128x32: 1024 float4)
    {
        uint2* db = (uint2*)Bs;
        const float4* sw = (const float4*)W;
        for (int i = tid; i < 1024; i += 256) {
            int r = i >> 3, c4 = i & 7;
            float4 f = sw[i];
            uint2 p;
            half2 h0 = __floats2half2_rn(f.x, f.y);
            half2 h1 = __floats2half2_rn(f.z, f.w);
            p.x = *(uint32_t*)&h0;
            p.y = *(uint32_t*)&h1;
            db[r * 10 + c4] = p;
        }
    }
    // stage A = g_agg1 tile
    {
        uint2* da = (uint2*)As;
        const float4* sa = (const float4*)g_agg1;
        for (int i = tid; i < 2048; i += 256) {
            int r = i >> 5, c4 = i & 31;
            int g = row0 + r;
            float4 f = (g < N) ? sa[(size_t)g * 32 + c4]
                               : make_float4(0.f, 0.f, 0.f, 0.f);
            uint2 p;
            half2 h0 = __floats2half2_rn(f.x, f.y);
            half2 h1 = __floats2half2_rn(f.z, f.w);
            p.x = *(uint32_t*)&h0;
            p.y = *(uint32_t*)&h1;
            da[r * 34 + c4] = p;
        }
    }
    __syncthreads();

    int w = tid >> 5;
    int wr = w & 3, wc = w >> 2;        // rows wr*16, cols wc*16
    wmma::fragment<wmma::accumulator, 16, 16, 16, float> acc;
    wmma::fill_fragment(acc, 0.f);

#pragma unroll
    for (int k = 0; k < 8; k++) {
        wmma::fragment<wmma::matrix_a, 16, 16, 16, __half, wmma::row_major> a;
        wmma::fragment<wmma::matrix_b, 16, 16, 16, __half, wmma::row_major> b;
        wmma::load_matrix_sync(a, As + (wr * 16) * LDA + k * 16, LDA);
        wmma::load_matrix_sync(b, Bs + (k * 16) * LDB2 + wc * 16, LDB2);
        wmma::mma_sync(acc, a, b, acc);
    }

    __syncthreads();
    wmma::store_matrix_sync(outs + (wr * 16) * 32 + wc * 16, acc, 32, wmma::mem_row_major);
    __syncthreads();

    for (int i = tid; i < 64 * 16; i += 256) {
        int r = i >> 4, c2 = i & 15;
        int g = row0 + r;
        if (g < N) {
            float2 f = ((const float2*)outs)[r * 16 + c2];
            ((half2*)g_h2h)[(size_t)g * 16 + c2] = __floats2half2_rn(f.x, f.y);
        }
    }

    float asv = att_s[lane];
    float adv = att_d[lane];
#pragma unroll
    for (int r8 = 0; r8 < 8; r8++) {
        int r = w * 8 + r8;
        int g = row0 + r;
        float hv = outs[r * 32 + lane];
        float ps = hv * asv;
        float pd = hv * adv;
#pragma unroll
        for (int o = 16; o > 0; o >>= 1) {
            ps += __shfl_xor_sync(0xFFFFFFFFu, ps, o);
            pd += __shfl_xor_sync(0xFFFFFFFFu, pd, o);
        }
        if (lane == 0 && g < N) {
            g_asrc2[g] = ps;
            g_adst2[g] = pd;
        }
    }
}

// ---------------- #5: layer-1 aggregation -------------------------------------
__global__ void agg1_kernel(const float* __restrict__ b1, int N, int EN) {
    int n = (blockIdx.x * blockDim.x + threadIdx.x) >> 5;
    int lane = threadIdx.x & 31;
    if (n >= N) return;
    if (lane == 0) g_cursor[n] = 0;     // self-heal
    int h = lane >> 3;
    float ad = g_adst1[n * 4 + h];
    int beg = g_rowfin[n];
    int end = (n + 1 < N) ? g_rowfin[n + 1] : EN;
    const uint2* hb = (const uint2*)g_h1h;

    float4 acc = make_float4(0.f, 0.f, 0.f, 0.f);
    float den = 0.f;

    for (int base = beg; base < end; base += 32) {
        int m = end - base; if (m > 32) m = 32;
        int sv = (base + lane < end) ? g_esrc[base + lane] : 0;
        int j = 0;
        for (; j + 4 <= m; j += 4) {
            int s0 = __shfl_sync(0xFFFFFFFFu, sv, j);
            int s1 = __shfl_sync(0xFFFFFFFFu, sv, j + 1);
            int s2 = __shfl_sync(0xFFFFFFFFu, sv, j + 2);
            int s3 = __shfl_sync(0xFFFFFFFFu, sv, j + 3);
            float e0 = g_asrc1[s0 * 4 + h] + ad;
            float e1 = g_asrc1[s1 * 4 + h] + ad;
            float e2 = g_asrc1[s2 * 4 + h] + ad;
            float e3 = g_asrc1[s3 * 4 + h] + ad;
            uint2 r0 = hb[s0 * 32 + lane];
            uint2 r1 = hb[s1 * 32 + lane];
            uint2 r2 = hb[s2 * 32 + lane];
            uint2 r3 = hb[s3 * 32 + lane];
            e0 = (e0 > 0.f) ? e0 : NEG_SLOPE * e0;
            e1 = (e1 > 0.f) ? e1 : NEG_SLOPE * e1;
            e2 = (e2 > 0.f) ? e2 : NEG_SLOPE * e2;
            e3 = (e3 > 0.f) ? e3 : NEG_SLOPE * e3;
            float x0 = __expf(e0), x1 = __expf(e1);
            float x2 = __expf(e2), x3 = __expf(e3);
            den += x0 + x1 + x2 + x3;
            float2 a0 = __half22float2(*(half2*)&r0.x);
            float2 a1 = __half22float2(*(half2*)&r0.y);
            float2 c0 = __half22float2(*(half2*)&r1.x);
            float2 c1 = __half22float2(*(half2*)&r1.y);
            float2 d0 = __half22float2(*(half2*)&r2.x);
            float2 d1 = __half22float2(*(half2*)&r2.y);
            float2 f0 = __half22float2(*(half2*)&r3.x);
            float2 f1 = __half22float2(*(half2*)&r3.y);
            acc.x += x0 * a0.x + x1 * c0.x + x2 * d0.x + x3 * f0.x;
            acc.y += x0 * a0.y + x1 * c0.y + x2 * d0.y + x3 * f0.y;
            acc.z += x0 * a1.x + x1 * c1.x + x2 * d1.x + x3 * f1.x;
            acc.w += x0 * a1.y + x1 * c1.y + x2 * d1.y + x3 * f1.y;
        }
        for (; j < m; j++) {
            int s = __shfl_sync(0xFFFFFFFFu, sv, j);
            float e = g_asrc1[s * 4 + h] + ad;
            e = (e > 0.f) ? e : NEG_SLOPE * e;
            float ex = __expf(e);
            uint2 r0 = hb[s * 32 + lane];
            float2 a0 = __half22float2(*(half2*)&r0.x);
            float2 a1 = __half22float2(*(half2*)&r0.y);
            den += ex;
            acc.x += ex * a0.x; acc.y += ex * a0.y;
            acc.z += ex * a1.x; acc.w += ex * a1.y;
        }
    }
    float inv = 1.f / (den + EPS);
    float4 bias = ((const float4*)b1)[lane];
    float4 r;
    r.x = fmaxf(acc.x * inv + bias.x, 0.f);
    r.y = fmaxf(acc.y * inv + bias.y, 0.f);
    r.z = fmaxf(acc.z * inv + bias.z, 0.f);
    r.w = fmaxf(acc.w * inv + bias.w, 0.f);
    ((float4*)g_agg1)[n * 32 + lane] = r;
}

// ---------------- #7: layer-2 aggregation -------------------------------------
__global__ void agg2_kernel(float* __restrict__ out,
                            const float* __restrict__ b2, int N, int EN) {
    int n = (blockIdx.x * blockDim.x + threadIdx.x) >> 5;
    int lane = threadIdx.x & 31;
    if (n >= N) return;
    float ad = g_adst2[n];
    int beg = g_rowfin[n];
    int end = (n + 1 < N) ? g_rowfin[n + 1] : EN;

    float acc = 0.f;
    float den = 0.f;
    for (int base = beg; base < end; base += 32) {
        int m = end - base; if (m > 32) m = 32;
        int sv = 0; float av = 0.f;
        if (base + lane < end) {
            sv = g_esrc[base + lane];
            av = g_asrc2[sv];
        }
        int j = 0;
        for (; j + 4 <= m; j += 4) {
            int s0 = __shfl_sync(0xFFFFFFFFu, sv, j);
            int s1 = __shfl_sync(0xFFFFFFFFu, sv, j + 1);
            int s2 = __shfl_sync(0xFFFFFFFFu, sv, j + 2);
            int s3 = __shfl_sync(0xFFFFFFFFu, sv, j + 3);
            float e0 = __shfl_sync(0xFFFFFFFFu, av, j) + ad;
            float e1 = __shfl_sync(0xFFFFFFFFu, av, j + 1) + ad;
            float e2 = __shfl_sync(0xFFFFFFFFu, av, j + 2) + ad;
            float e3 = __shfl_sync(0xFFFFFFFFu, av, j + 3) + ad;
            float v0 = __half2float(g_h2h[s0 * 32 + lane]);
            float v1 = __half2float(g_h2h[s1 * 32 + lane]);
            float v2 = __half2float(g_h2h[s2 * 32 + lane]);
            float v3 = __half2float(g_h2h[s3 * 32 + lane]);
            e0 = (e0 > 0.f) ? e0 : NEG_SLOPE * e0;
            e1 = (e1 > 0.f) ? e1 : NEG_SLOPE * e1;
            e2 = (e2 > 0.f) ? e2 : NEG_SLOPE * e2;
            e3 = (e3 > 0.f) ? e3 : NEG_SLOPE * e3;
            float x0 = __expf(e0), x1 = __expf(e1);
            float x2 = __expf(e2), x3 = __expf(e3);
            den += x0 + x1 + x2 + x3;
            acc += x0 * v0 + x1 * v1 + x2 * v2 + x3 * v3;
        }
        for (; j < m; j++) {
            int s = __shfl_sync(0xFFFFFFFFu, sv, j);
            float e = __shfl_sync(0xFFFFFFFFu, av, j) + ad;
            e = (e > 0.f) ? e : NEG_SLOPE * e;
            float ex = __expf(e);
            den += ex;
            acc += ex * __half2float(g_h2h[s * 32 + lane]);
        }
    }
    out[n * 32 + lane] = acc / (den + EPS) + b2[lane];
}

// ---------------- launch ------------------------------------------------------
extern "C" void kernel_launch(void* const* d_in, const int* in_sizes, int n_in,
                              void* d_out, int out_size) {
    const float* x      = (const float*)d_in[0];
    const int*   ei     = (const int*)  d_in[1];
    const float* W1     = (const float*)d_in[2];
    const float* att_s1 = (const float*)d_in[3];
    const float* att_d1 = (const float*)d_in[4];
    const float* b1     = (const float*)d_in[5];
    const float* W2     = (const float*)d_in[6];
    const float* att_s2 = (const float*)d_in[7];
    const float* att_d2 = (const float*)d_in[8];
    const float* b2     = (const float*)d_in[9];

    int N = in_sizes[0] / IN_DIM;
    int E = in_sizes[1] / 2;
    const int* src = ei;
    const int* dst = ei + E;
    float* out = (float*)d_out;
    int EN = E + N;
    int NB = (N + 1023) / 1024;

    static bool init_done = false;
    if (!init_done) {
        cudaFuncSetAttribute(gemm1_kernel, cudaFuncAttributeMaxDynamicSharedMemorySize, GEMM1_SMEM);
        cudaFuncSetAttribute(gemm2_kernel, cudaFuncAttributeMaxDynamicSharedMemorySize, GEMM2_SMEM);
        init_done = true;
    }

    // #1..#3: CSR build
    hist_kernel<<<(EN + 255) / 256, 256>>>(dst, E, EN);
    scan1_kernel<<<NB, 1024>>>(N);
    scatter_kernel<<<(EN + 255) / 256, 256>>>(src, dst, E, EN);

    // #4: gemm1  <-- ncu captures launch #4
    gemm1_kernel<<<(N + 63) / 64, 256, GEMM1_SMEM>>>(x, W1, att_s1, att_d1, N);
    // #5: agg1
    agg1_kernel<<<(N * 32 + 255) / 256, 256>>>(b1, N, EN);
    // #6, #7: layer 2
    gemm2_kernel<<<(N + 63) / 64, 256, GEMM2_SMEM>>>(W2, att_s2, att_d2, N);
    agg2_kernel<<<(N * 32 + 255) / 256, 256>>>(out, b2, N, EN);
}

// round 11
// speedup vs baseline: 1.5660x; 1.5660x over previous
#include <cuda_runtime.h>
#include <cuda_fp16.h>
#include <mma.h>
#include <stdint.h>

using namespace nvcuda;

#define MAXN 100000
#define NPAD (MAXN + 64)
#define MAXE 1600000
#define IN_DIM 128
#define HC 128
#define OUT_DIM 32
#define HEADS 4
#define NEG_SLOPE 0.2f
#define EPS 1e-16f

#define LDA 136                       // half elems per A row (17 uint4)
#define LDB1 136
#define LDB2 40                       // 5 uint4
#define GEMM1_SMEM (64*LDA*2 + 128*LDB1*2)   // 52224 B (>= 32KB fp32 out stage)
#define GEMM2_SMEM (64*LDA*2 + 128*LDB2*2)   // 27648 B (>= 8KB out stage)

// ---------------- scratch (device globals; zero-init at load) ----------------
__device__ __half g_xh[MAXN * IN_DIM];     // fp16 copy of x
__device__ __half g_h1h[NPAD * HC];        // h1 fp16 (gather payload)
__device__ __half g_agg1h[NPAD * HC];      // h1' fp16 (gemm2 input)
__device__ __half g_h2h[NPAD * OUT_DIM];   // h2 fp16
__device__ __half g_W1h[IN_DIM * HC];      // fp16 W1
__device__ __half g_W2h[HC * OUT_DIM];     // fp16 W2
__device__ float g_asrc1[MAXN * HEADS];
__device__ float g_adst1[MAXN * HEADS];
__device__ float g_asrc2[MAXN];
__device__ float g_adst2[MAXN];
// CSR scratch (deg/cursor self-healing; btot[NB..127] stays 0 from load)
__device__ int g_deg[MAXN];
__device__ int g_rowptr[MAXN + 1];
__device__ int g_rowfin[MAXN];
__device__ int g_cursor[MAXN];
__device__ int g_esrc[MAXE + MAXN];
__device__ int g_btot[128];

// ---------------- #1: histogram + fp16 conversion of x/W1/W2 ------------------
__global__ void hist_kernel(const int* __restrict__ dst,
                            const float* __restrict__ x,
                            const float* __restrict__ W1,
                            const float* __restrict__ W2,
                            int E, int EN, int N) {
    int t = blockIdx.x * blockDim.x + threadIdx.x;
    int stride = gridDim.x * blockDim.x;

    // convert x, W1, W2 (float4 granules -> uint2 of half2s)
    int nx4 = N * 32;              // x float4 count
    int nw1 = 128 * 32;            // W1 float4 count (4096)
    int nw2 = 128 * 8;             // W2 float4 count (1024)
    int tot = nx4 + nw1 + nw2;
    for (int i = t; i < tot; i += stride) {
        float4 f;
        uint2* dp;
        if (i < nx4) {
            f = ((const float4*)x)[i];
            dp = (uint2*)g_xh + i;
        } else if (i < nx4 + nw1) {
            f = ((const float4*)W1)[i - nx4];
            dp = (uint2*)g_W1h + (i - nx4);
        } else {
            f = ((const float4*)W2)[i - nx4 - nw1];
            dp = (uint2*)g_W2h + (i - nx4 - nw1);
        }
        half2 h0 = __floats2half2_rn(f.x, f.y);
        half2 h1 = __floats2half2_rn(f.z, f.w);
        uint2 p;
        p.x = *(uint32_t*)&h0;
        p.y = *(uint32_t*)&h1;
        *dp = p;
    }

    if (t >= EN) return;
    int d = (t < E) ? dst[t] : (t - E);
    atomicAdd(&g_deg[d], 1);
}

// ---------------- #2: per-block scan ------------------------------------------
__global__ void scan1_kernel(int N) {
    __shared__ int sh[1024];
    int i = blockIdx.x * 1024 + threadIdx.x;
    int v = (i < N) ? g_deg[i] : 0;
    if (i < N) g_deg[i] = 0;            // self-heal
    sh[threadIdx.x] = v;
    __syncthreads();
#pragma unroll
    for (int off = 1; off < 1024; off <<= 1) {
        int t = (threadIdx.x >= off) ? sh[threadIdx.x - off] : 0;
        __syncthreads();
        sh[threadIdx.x] += t;
        __syncthreads();
    }
    if (i < N) g_rowptr[i] = sh[threadIdx.x] - v;
    if (threadIdx.x == 1023) g_btot[blockIdx.x] = sh[1023];
}

// ---------------- #3: scatter (inline btot scan, writes rowfin) ---------------
__global__ void scatter_kernel(const int* __restrict__ src,
                               const int* __restrict__ dst, int E, int EN) {
    __shared__ int boff[128];
    if (threadIdx.x < 128) boff[threadIdx.x] = g_btot[threadIdx.x];
    __syncthreads();
    if (threadIdx.x < 128) {
        int v = boff[threadIdx.x];
        int acc = v;
#pragma unroll
        for (int off = 1; off < 128; off <<= 1) {
            int u = (threadIdx.x >= off) ? boff[threadIdx.x - off] : 0;
            __syncthreads();
            boff[threadIdx.x] = acc = acc + u;
            __syncthreads();
        }
        boff[threadIdx.x] = acc - v;
    } else {
#pragma unroll
        for (int off = 1; off < 128; off <<= 1) { __syncthreads(); __syncthreads(); }
    }
    __syncthreads();

    int t = blockIdx.x * blockDim.x + threadIdx.x;
    if (t >= EN) return;
    int s, d;
    if (t < E) { s = src[t]; d = dst[t]; }
    else       { s = t - E;  d = s; }
    int base = g_rowptr[d] + boff[d >> 10];
    g_rowfin[d] = base;
    int pos = base + atomicAdd(&g_cursor[d], 1);
    g_esrc[pos] = s;
}

// ---------------- #4: GEMM1 (fp16 WMMA, pure-copy staging) + attn1 ------------
__global__ void gemm1_kernel(const float* __restrict__ att_s,
                             const float* __restrict__ att_d, int N) {
    extern __shared__ __half smh[];
    __half* As = smh;                   // 64 x LDA
    __half* Bs = smh + 64 * LDA;        // 128 x LDB1
    float* outs = (float*)smh;          // reused after MMA: 64*128 fp32 = 32KB
    int tid = threadIdx.x;
    int row0 = blockIdx.x * 64;

    // stage W1 (2048 uint4)
    {
        uint4* db = (uint4*)Bs;
        const uint4* sw = (const uint4*)g_W1h;
        for (int i = tid; i < 2048; i += 256) {
            int r = i >> 4, c = i & 15;
            db[r * 17 + c] = sw[i];
        }
    }
    // stage x tile (1024 uint4)
    {
        uint4* da = (uint4*)As;
        const uint4* sx = (const uint4*)g_xh;
        uint4 z = make_uint4(0u, 0u, 0u, 0u);
        for (int i = tid; i < 1024; i += 256) {
            int r = i >> 4, c = i & 15;
            int g = row0 + r;
            da[r * 17 + c] = (g < N) ? sx[(size_t)g * 16 + c] : z;
        }
    }
    __syncthreads();

    int w = tid >> 5;
    int lane = tid & 31;
    int wr = w >> 1, wc = w & 1;
    wmma::fragment<wmma::accumulator, 16, 16, 16, float> acc[4];
#pragma unroll
    for (int i = 0; i < 4; i++) wmma::fill_fragment(acc[i], 0.f);

#pragma unroll
    for (int k = 0; k < 8; k++) {
        wmma::fragment<wmma::matrix_a, 16, 16, 16, __half, wmma::row_major> a;
        wmma::load_matrix_sync(a, As + (wr * 16) * LDA + k * 16, LDA);
#pragma unroll
        for (int ct = 0; ct < 4; ct++) {
            wmma::fragment<wmma::matrix_b, 16, 16, 16, __half, wmma::row_major> b;
            wmma::load_matrix_sync(b, Bs + (k * 16) * LDB1 + wc * 64 + ct * 16, LDB1);
            wmma::mma_sync(acc[ct], a, b, acc[ct]);
        }
    }

    __syncthreads();
#pragma unroll
    for (int ct = 0; ct < 4; ct++)
        wmma::store_matrix_sync(outs + (wr * 16) * 128 + wc * 64 + ct * 16,
                                acc[ct], 128, wmma::mem_row_major);
    __syncthreads();

    // fp16 global store of h1
    for (int i = tid; i < 64 * 64; i += 256) {
        int r = i >> 6, c2 = i & 63;
        int g = row0 + r;
        if (g < N) {
            float2 f = ((const float2*)outs)[r * 64 + c2];
            ((half2*)g_h1h)[(size_t)g * 64 + c2] = __floats2half2_rn(f.x, f.y);
        }
    }

    // fused attn1
    float4 as = ((const float4*)att_s)[lane];
    float4 ad = ((const float4*)att_d)[lane];
#pragma unroll
    for (int r8 = 0; r8 < 8; r8++) {
        int r = w * 8 + r8;
        int g = row0 + r;
        float4 hv = ((const float4*)outs)[r * 32 + lane];
        float ps = hv.x * as.x + hv.y * as.y + hv.z * as.z + hv.w * as.w;
        float pd = hv.x * ad.x + hv.y * ad.y + hv.z * ad.z + hv.w * ad.w;
        ps += __shfl_xor_sync(0xFFFFFFFFu, ps, 1);
        pd += __shfl_xor_sync(0xFFFFFFFFu, pd, 1);
        ps += __shfl_xor_sync(0xFFFFFFFFu, ps, 2);
        pd += __shfl_xor_sync(0xFFFFFFFFu, pd, 2);
        ps += __shfl_xor_sync(0xFFFFFFFFu, ps, 4);
        pd += __shfl_xor_sync(0xFFFFFFFFu, pd, 4);
        if ((lane & 7) == 0 && g < N) {
            int h = lane >> 3;
            g_asrc1[g * 4 + h] = ps;
            g_adst1[g * 4 + h] = pd;
        }
    }
}

// ---------------- #6: GEMM2 (fp16 WMMA, pure-copy staging) + attn2 ------------
__global__ void gemm2_kernel(const float* __restrict__ att_s,
                             const float* __restrict__ att_d, int N) {
    extern __shared__ __half smh[];
    __half* As = smh;                   // 64 x LDA
    __half* Bs = smh + 64 * LDA;        // 128 x LDB2
    float* outs = (float*)smh;          // reused: 64*32 fp32 = 8KB
    int tid = threadIdx.x;
    int lane = tid & 31;
    int row0 = blockIdx.x * 64;

    // stage W2 (512 uint4)
    {
        uint4* db = (uint4*)Bs;
        const uint4* sw = (const uint4*)g_W2h;
        for (int i = tid; i < 512; i += 256) {
            int r = i >> 2, c = i & 3;
            db[r * 5 + c] = sw[i];
        }
    }
    // stage A = h1' fp16 tile (1024 uint4)
    {
        uint4* da = (uint4*)As;
        const uint4* sa = (const uint4*)g_agg1h;
        uint4 z = make_uint4(0u, 0u, 0u, 0u);
        for (int i = tid; i < 1024; i += 256) {
            int r = i >> 4, c = i & 15;
            int g = row0 + r;
            da[r * 17 + c] = (g < N) ? sa[(size_t)g * 16 + c] : z;
        }
    }
    __syncthreads();

    int w = tid >> 5;
    int wr = w & 3, wc = w >> 2;
    wmma::fragment<wmma::accumulator, 16, 16, 16, float> acc;
    wmma::fill_fragment(acc, 0.f);

#pragma unroll
    for (int k = 0; k < 8; k++) {
        wmma::fragment<wmma::matrix_a, 16, 16, 16, __half, wmma::row_major> a;
        wmma::fragment<wmma::matrix_b, 16, 16, 16, __half, wmma::row_major> b;
        wmma::load_matrix_sync(a, As + (wr * 16) * LDA + k * 16, LDA);
        wmma::load_matrix_sync(b, Bs + (k * 16) * LDB2 + wc * 16, LDB2);
        wmma::mma_sync(acc, a, b, acc);
    }

    __syncthreads();
    wmma::store_matrix_sync(outs + (wr * 16) * 32 + wc * 16, acc, 32, wmma::mem_row_major);
    __syncthreads();

    for (int i = tid; i < 64 * 16; i += 256) {
        int r = i >> 4, c2 = i & 15;
        int g = row0 + r;
        if (g < N) {
            float2 f = ((const float2*)outs)[r * 16 + c2];
            ((half2*)g_h2h)[(size_t)g * 16 + c2] = __floats2half2_rn(f.x, f.y);
        }
    }

    float asv = att_s[lane];
    float adv = att_d[lane];
#pragma unroll
    for (int r8 = 0; r8 < 8; r8++) {
        int r = w * 8 + r8;
        int g = row0 + r;
        float hv = outs[r * 32 + lane];
        float ps = hv * asv;
        float pd = hv * adv;
#pragma unroll
        for (int o = 16; o > 0; o >>= 1) {
            ps += __shfl_xor_sync(0xFFFFFFFFu, ps, o);
            pd += __shfl_xor_sync(0xFFFFFFFFu, pd, o);
        }
        if (lane == 0 && g < N) {
            g_asrc2[g] = ps;
            g_adst2[g] = pd;
        }
    }
}

// ---------------- #5: layer-1 aggregation (writes fp16 h1') -------------------
__global__ void agg1_kernel(const float* __restrict__ b1, int N, int EN) {
    int n = (blockIdx.x * blockDim.x + threadIdx.x) >> 5;
    int lane = threadIdx.x & 31;
    if (n >= N) return;
    if (lane == 0) g_cursor[n] = 0;     // self-heal
    int h = lane >> 3;
    float ad = g_adst1[n * 4 + h];
    int beg = g_rowfin[n];
    int end = (n + 1 < N) ? g_rowfin[n + 1] : EN;
    const uint2* hb = (const uint2*)g_h1h;

    float4 acc = make_float4(0.f, 0.f, 0.f, 0.f);
    float den = 0.f;

    for (int base = beg; base < end; base += 32) {
        int m = end - base; if (m > 32) m = 32;
        int sv = (base + lane < end) ? g_esrc[base + lane] : 0;
        int j = 0;
        for (; j + 4 <= m; j += 4) {
            int s0 = __shfl_sync(0xFFFFFFFFu, sv, j);
            int s1 = __shfl_sync(0xFFFFFFFFu, sv, j + 1);
            int s2 = __shfl_sync(0xFFFFFFFFu, sv, j + 2);
            int s3 = __shfl_sync(0xFFFFFFFFu, sv, j + 3);
            float e0 = g_asrc1[s0 * 4 + h] + ad;
            float e1 = g_asrc1[s1 * 4 + h] + ad;
            float e2 = g_asrc1[s2 * 4 + h] + ad;
            float e3 = g_asrc1[s3 * 4 + h] + ad;
            uint2 r0 = hb[s0 * 32 + lane];
            uint2 r1 = hb[s1 * 32 + lane];
            uint2 r2 = hb[s2 * 32 + lane];
            uint2 r3 = hb[s3 * 32 + lane];
            e0 = (e0 > 0.f) ? e0 : NEG_SLOPE * e0;
            e1 = (e1 > 0.f) ? e1 : NEG_SLOPE * e1;
            e2 = (e2 > 0.f) ? e2 : NEG_SLOPE * e2;
            e3 = (e3 > 0.f) ? e3 : NEG_SLOPE * e3;
            float x0 = __expf(e0), x1 = __expf(e1);
            float x2 = __expf(e2), x3 = __expf(e3);
            den += x0 + x1 + x2 + x3;
            float2 a0 = __half22float2(*(half2*)&r0.x);
            float2 a1 = __half22float2(*(half2*)&r0.y);
            float2 c0 = __half22float2(*(half2*)&r1.x);
            float2 c1 = __half22float2(*(half2*)&r1.y);
            float2 d0 = __half22float2(*(half2*)&r2.x);
            float2 d1 = __half22float2(*(half2*)&r2.y);
            float2 f0 = __half22float2(*(half2*)&r3.x);
            float2 f1 = __half22float2(*(half2*)&r3.y);
            acc.x += x0 * a0.x + x1 * c0.x + x2 * d0.x + x3 * f0.x;
            acc.y += x0 * a0.y + x1 * c0.y + x2 * d0.y + x3 * f0.y;
            acc.z += x0 * a1.x + x1 * c1.x + x2 * d1.x + x3 * f1.x;
            acc.w += x0 * a1.y + x1 * c1.y + x2 * d1.y + x3 * f1.y;
        }
        for (; j < m; j++) {
            int s = __shfl_sync(0xFFFFFFFFu, sv, j);
            float e = g_asrc1[s * 4 + h] + ad;
            e = (e > 0.f) ? e : NEG_SLOPE * e;
            float ex = __expf(e);
            uint2 r0 = hb[s * 32 + lane];
            float2 a0 = __half22float2(*(half2*)&r0.x);
            float2 a1 = __half22float2(*(half2*)&r0.y);
            den += ex;
            acc.x += ex * a0.x; acc.y += ex * a0.y;
            acc.z += ex * a1.x; acc.w += ex * a1.y;
        }
    }
    float inv = 1.f / (den + EPS);
    float4 bias = ((const float4*)b1)[lane];
    float rx = fmaxf(acc.x * inv + bias.x, 0.f);
    float ry = fmaxf(acc.y * inv + bias.y, 0.f);
    float rz = fmaxf(acc.z * inv + bias.z, 0.f);
    float rw = fmaxf(acc.w * inv + bias.w, 0.f);
    half2 h0 = __floats2half2_rn(rx, ry);
    half2 h1 = __floats2half2_rn(rz, rw);
    uint2 p;
    p.x = *(uint32_t*)&h0;
    p.y = *(uint32_t*)&h1;
    ((uint2*)g_agg1h)[n * 32 + lane] = p;
}

// ---------------- #7: layer-2 aggregation -------------------------------------
__global__ void agg2_kernel(float* __restrict__ out,
                            const float* __restrict__ b2, int N, int EN) {
    int n = (blockIdx.x * blockDim.x + threadIdx.x) >> 5;
    int lane = threadIdx.x & 31;
    if (n >= N) return;
    float ad = g_adst2[n];
    int beg = g_rowfin[n];
    int end = (n + 1 < N) ? g_rowfin[n + 1] : EN;

    float acc = 0.f;
    float den = 0.f;
    for (int base = beg; base < end; base += 32) {
        int m = end - base; if (m > 32) m = 32;
        int sv = 0; float av = 0.f;
        if (base + lane < end) {
            sv = g_esrc[base + lane];
            av = g_asrc2[sv];
        }
        int j = 0;
        for (; j + 4 <= m; j += 4) {
            int s0 = __shfl_sync(0xFFFFFFFFu, sv, j);
            int s1 = __shfl_sync(0xFFFFFFFFu, sv, j + 1);
            int s2 = __shfl_sync(0xFFFFFFFFu, sv, j + 2);
            int s3 = __shfl_sync(0xFFFFFFFFu, sv, j + 3);
            float e0 = __shfl_sync(0xFFFFFFFFu, av, j) + ad;
            float e1 = __shfl_sync(0xFFFFFFFFu, av, j + 1) + ad;
            float e2 = __shfl_sync(0xFFFFFFFFu, av, j + 2) + ad;
            float e3 = __shfl_sync(0xFFFFFFFFu, av, j + 3) + ad;
            float v0 = __half2float(g_h2h[s0 * 32 + lane]);
            float v1 = __half2float(g_h2h[s1 * 32 + lane]);
            float v2 = __half2float(g_h2h[s2 * 32 + lane]);
            float v3 = __half2float(g_h2h[s3 * 32 + lane]);
            e0 = (e0 > 0.f) ? e0 : NEG_SLOPE * e0;
            e1 = (e1 > 0.f) ? e1 : NEG_SLOPE * e1;
            e2 = (e2 > 0.f) ? e2 : NEG_SLOPE * e2;
            e3 = (e3 > 0.f) ? e3 : NEG_SLOPE * e3;
            float x0 = __expf(e0), x1 = __expf(e1);
            float x2 = __expf(e2), x3 = __expf(e3);
            den += x0 + x1 + x2 + x3;
            acc += x0 * v0 + x1 * v1 + x2 * v2 + x3 * v3;
        }
        for (; j < m; j++) {
            int s = __shfl_sync(0xFFFFFFFFu, sv, j);
            float e = __shfl_sync(0xFFFFFFFFu, av, j) + ad;
            e = (e > 0.f) ? e : NEG_SLOPE * e;
            float ex = __expf(e);
            den += ex;
            acc += ex * __half2float(g_h2h[s * 32 + lane]);
        }
    }
    out[n * 32 + lane] = acc / (den + EPS) + b2[lane];
}

// ---------------- launch ------------------------------------------------------
extern "C" void kernel_launch(void* const* d_in, const int* in_sizes, int n_in,
                              void* d_out, int out_size) {
    const float* x      = (const float*)d_in[0];
    const int*   ei     = (const int*)  d_in[1];
    const float* W1     = (const float*)d_in[2];
    const float* att_s1 = (const float*)d_in[3];
    const float* att_d1 = (const float*)d_in[4];
    const float* b1     = (const float*)d_in[5];
    const float* W2     = (const float*)d_in[6];
    const float* att_s2 = (const float*)d_in[7];
    const float* att_d2 = (const float*)d_in[8];
    const float* b2     = (const float*)d_in[9];

    int N = in_sizes[0] / IN_DIM;
    int E = in_sizes[1] / 2;
    const int* src = ei;
    const int* dst = ei + E;
    float* out = (float*)d_out;
    int EN = E + N;
    int NB = (N + 1023) / 1024;

    static bool init_done = false;
    if (!init_done) {
        cudaFuncSetAttribute(gemm1_kernel, cudaFuncAttributeMaxDynamicSharedMemorySize, GEMM1_SMEM);
        cudaFuncSetAttribute(gemm2_kernel, cudaFuncAttributeMaxDynamicSharedMemorySize, GEMM2_SMEM);
        init_done = true;
    }

    // #1..#3: CSR build (+fp16 conversion folded into #1)
    hist_kernel<<<(EN + 255) / 256, 256>>>(dst, x, W1, W2, E, EN, N);
    scan1_kernel<<<NB, 1024>>>(N);
    scatter_kernel<<<(EN + 255) / 256, 256>>>(src, dst, E, EN);

    // #4: gemm1  <-- ncu captures launch #4
    gemm1_kernel<<<(N + 63) / 64, 256, GEMM1_SMEM>>>(att_s1, att_d1, N);
    // #5: agg1
    agg1_kernel<<<(N * 32 + 255) / 256, 256>>>(b1, N, EN);
    // #6, #7: layer 2
    gemm2_kernel<<<(N + 63) / 64, 256, GEMM2_SMEM>>>(att_s2, att_d2, N);
    agg2_kernel<<<(N * 32 + 255) / 256, 256>>>(out, b2, N, EN);
}

// round 12
// speedup vs baseline: 1.5748x; 1.0056x over previous
#include <cuda_runtime.h>
#include <cuda_fp16.h>
#include <mma.h>
#include <stdint.h>

using namespace nvcuda;

#define MAXN 100000
#define NPAD (MAXN + 64)
#define MAXE 1600000
#define IN_DIM 128
#define HC 128
#define OUT_DIM 32
#define HEADS 4
#define NEG_SLOPE 0.2f
#define EPS 1e-16f

#define LDA 136                       // half elems per A row (17 uint4)
#define LDB1 136
#define LDB2 40                       // 5 uint4
#define GEMM1_SMEM (64*LDA*2 + 128*LDB1*2)   // 52224 B (>= 32KB fp32 out stage)
#define GEMM2_SMEM (64*LDA*2 + 128*LDB2*2)   // 27648 B (>= 8KB out stage)

// ---------------- scratch (device globals; zero-init at load) ----------------
__device__ __half g_xh[MAXN * IN_DIM];     // fp16 copy of x
__device__ __half g_h1h[NPAD * HC];        // h1 fp16 (gather payload)
__device__ __half g_agg1h[NPAD * HC];      // h1' fp16 (gemm2 input)
__device__ __half g_h2h[NPAD * OUT_DIM];   // h2 fp16
__device__ __half g_W1h[IN_DIM * HC];      // fp16 W1
__device__ __half g_W2h[HC * OUT_DIM];     // fp16 W2
__device__ float g_asrc1[MAXN * HEADS];
__device__ float g_adst1[MAXN * HEADS];
__device__ float g_asrc2[MAXN];
__device__ float g_adst2[MAXN];
// CSR scratch (deg/cursor self-healing; btot[NB..127] stays 0 from load)
__device__ int g_deg[MAXN];
__device__ int g_rowptr[MAXN + 1];
__device__ int g_rowfin[MAXN];
__device__ int g_cursor[MAXN];
__device__ int g_esrc[MAXE + MAXN];
__device__ int g_btot[128];

// ---------------- fp16 conversion of x/W1/W2 (dense-chain stream) -------------
__global__ void conv_kernel(const float* __restrict__ x,
                            const float* __restrict__ W1,
                            const float* __restrict__ W2, int N) {
    int t = blockIdx.x * blockDim.x + threadIdx.x;
    int stride = gridDim.x * blockDim.x;
    int nx4 = N * 32;
    int nw1 = 128 * 32;
    int nw2 = 128 * 8;
    int tot = nx4 + nw1 + nw2;
    for (int i = t; i < tot; i += stride) {
        float4 f;
        uint2* dp;
        if (i < nx4) {
            f = ((const float4*)x)[i];
            dp = (uint2*)g_xh + i;
        } else if (i < nx4 + nw1) {
            f = ((const float4*)W1)[i - nx4];
            dp = (uint2*)g_W1h + (i - nx4);
        } else {
            f = ((const float4*)W2)[i - nx4 - nw1];
            dp = (uint2*)g_W2h + (i - nx4 - nw1);
        }
        half2 h0 = __floats2half2_rn(f.x, f.y);
        half2 h1 = __floats2half2_rn(f.z, f.w);
        uint2 p;
        p.x = *(uint32_t*)&h0;
        p.y = *(uint32_t*)&h1;
        *dp = p;
    }
}

// ---------------- CSR chain (side stream) --------------------------------------
__global__ void hist_kernel(const int* __restrict__ dst, int E, int EN) {
    int t = blockIdx.x * blockDim.x + threadIdx.x;
    if (t >= EN) return;
    int d = (t < E) ? dst[t] : (t - E);
    atomicAdd(&g_deg[d], 1);
}

__global__ void scan1_kernel(int N) {
    __shared__ int sh[1024];
    int i = blockIdx.x * 1024 + threadIdx.x;
    int v = (i < N) ? g_deg[i] : 0;
    if (i < N) g_deg[i] = 0;            // self-heal
    sh[threadIdx.x] = v;
    __syncthreads();
#pragma unroll
    for (int off = 1; off < 1024; off <<= 1) {
        int t = (threadIdx.x >= off) ? sh[threadIdx.x - off] : 0;
        __syncthreads();
        sh[threadIdx.x] += t;
        __syncthreads();
    }
    if (i < N) g_rowptr[i] = sh[threadIdx.x] - v;
    if (threadIdx.x == 1023) g_btot[blockIdx.x] = sh[1023];
}

__global__ void scatter_kernel(const int* __restrict__ src,
                               const int* __restrict__ dst, int E, int EN) {
    __shared__ int boff[128];
    if (threadIdx.x < 128) boff[threadIdx.x] = g_btot[threadIdx.x];
    __syncthreads();
    if (threadIdx.x < 128) {
        int v = boff[threadIdx.x];
        int acc = v;
#pragma unroll
        for (int off = 1; off < 128; off <<= 1) {
            int u = (threadIdx.x >= off) ? boff[threadIdx.x - off] : 0;
            __syncthreads();
            boff[threadIdx.x] = acc = acc + u;
            __syncthreads();
        }
        boff[threadIdx.x] = acc - v;
    } else {
#pragma unroll
        for (int off = 1; off < 128; off <<= 1) { __syncthreads(); __syncthreads(); }
    }
    __syncthreads();

    int t = blockIdx.x * blockDim.x + threadIdx.x;
    if (t >= EN) return;
    int s, d;
    if (t < E) { s = src[t]; d = dst[t]; }
    else       { s = t - E;  d = s; }
    int base = g_rowptr[d] + boff[d >> 10];
    g_rowfin[d] = base;
    int pos = base + atomicAdd(&g_cursor[d], 1);
    g_esrc[pos] = s;
}

// ---------------- GEMM1 (fp16 WMMA, pure-copy staging) + attn1 ----------------
__global__ void gemm1_kernel(const float* __restrict__ att_s,
                             const float* __restrict__ att_d, int N) {
    extern __shared__ __half smh[];
    __half* As = smh;                   // 64 x LDA
    __half* Bs = smh + 64 * LDA;        // 128 x LDB1
    float* outs = (float*)smh;          // reused after MMA: 64*128 fp32 = 32KB
    int tid = threadIdx.x;
    int row0 = blockIdx.x * 64;

    // stage W1 (2048 uint4)
    {
        uint4* db = (uint4*)Bs;
        const uint4* sw = (const uint4*)g_W1h;
        for (int i = tid; i < 2048; i += 256) {
            int r = i >> 4, c = i & 15;
            db[r * 17 + c] = sw[i];
        }
    }
    // stage x tile (1024 uint4)
    {
        uint4* da = (uint4*)As;
        const uint4* sx = (const uint4*)g_xh;
        uint4 z = make_uint4(0u, 0u, 0u, 0u);
        for (int i = tid; i < 1024; i += 256) {
            int r = i >> 4, c = i & 15;
            int g = row0 + r;
            da[r * 17 + c] = (g < N) ? sx[(size_t)g * 16 + c] : z;
        }
    }
    __syncthreads();

    int w = tid >> 5;
    int lane = tid & 31;
    int wr = w >> 1, wc = w & 1;
    wmma::fragment<wmma::accumulator, 16, 16, 16, float> acc[4];
#pragma unroll
    for (int i = 0; i < 4; i++) wmma::fill_fragment(acc[i], 0.f);

#pragma unroll
    for (int k = 0; k < 8; k++) {
        wmma::fragment<wmma::matrix_a, 16, 16, 16, __half, wmma::row_major> a;
        wmma::load_matrix_sync(a, As + (wr * 16) * LDA + k * 16, LDA);
#pragma unroll
        for (int ct = 0; ct < 4; ct++) {
            wmma::fragment<wmma::matrix_b, 16, 16, 16, __half, wmma::row_major> b;
            wmma::load_matrix_sync(b, Bs + (k * 16) * LDB1 + wc * 64 + ct * 16, LDB1);
            wmma::mma_sync(acc[ct], a, b, acc[ct]);
        }
    }

    __syncthreads();
#pragma unroll
    for (int ct = 0; ct < 4; ct++)
        wmma::store_matrix_sync(outs + (wr * 16) * 128 + wc * 64 + ct * 16,
                                acc[ct], 128, wmma::mem_row_major);
    __syncthreads();

    // fp16 global store of h1
    for (int i = tid; i < 64 * 64; i += 256) {
        int r = i >> 6, c2 = i & 63;
        int g = row0 + r;
        if (g < N) {
            float2 f = ((const float2*)outs)[r * 64 + c2];
            ((half2*)g_h1h)[(size_t)g * 64 + c2] = __floats2half2_rn(f.x, f.y);
        }
    }

    // fused attn1
    float4 as = ((const float4*)att_s)[lane];
    float4 ad = ((const float4*)att_d)[lane];
#pragma unroll
    for (int r8 = 0; r8 < 8; r8++) {
        int r = w * 8 + r8;
        int g = row0 + r;
        float4 hv = ((const float4*)outs)[r * 32 + lane];
        float ps = hv.x * as.x + hv.y * as.y + hv.z * as.z + hv.w * as.w;
        float pd = hv.x * ad.x + hv.y * ad.y + hv.z * ad.z + hv.w * ad.w;
        ps += __shfl_xor_sync(0xFFFFFFFFu, ps, 1);
        pd += __shfl_xor_sync(0xFFFFFFFFu, pd, 1);
        ps += __shfl_xor_sync(0xFFFFFFFFu, ps, 2);
        pd += __shfl_xor_sync(0xFFFFFFFFu, pd, 2);
        ps += __shfl_xor_sync(0xFFFFFFFFu, ps, 4);
        pd += __shfl_xor_sync(0xFFFFFFFFu, pd, 4);
        if ((lane & 7) == 0 && g < N) {
            int h = lane >> 3;
            g_asrc1[g * 4 + h] = ps;
            g_adst1[g * 4 + h] = pd;
        }
    }
}

// ---------------- GEMM2 (fp16 WMMA) + attn2 ------------------------------------
__global__ void gemm2_kernel(const float* __restrict__ att_s,
                             const float* __restrict__ att_d, int N) {
    extern __shared__ __half smh[];
    __half* As = smh;                   // 64 x LDA
    __half* Bs = smh + 64 * LDA;        // 128 x LDB2
    float* outs = (float*)smh;          // reused: 64*32 fp32 = 8KB
    int tid = threadIdx.x;
    int lane = tid & 31;
    int row0 = blockIdx.x * 64;

    // stage W2 (512 uint4)
    {
        uint4* db = (uint4*)Bs;
        const uint4* sw = (const uint4*)g_W2h;
        for (int i = tid; i < 512; i += 256) {
            int r = i >> 2, c = i & 3;
            db[r * 5 + c] = sw[i];
        }
    }
    // stage A = h1' fp16 tile (1024 uint4)
    {
        uint4* da = (uint4*)As;
        const uint4* sa = (const uint4*)g_agg1h;
        uint4 z = make_uint4(0u, 0u, 0u, 0u);
        for (int i = tid; i < 1024; i += 256) {
            int r = i >> 4, c = i & 15;
            int g = row0 + r;
            da[r * 17 + c] = (g < N) ? sa[(size_t)g * 16 + c] : z;
        }
    }
    __syncthreads();

    int w = tid >> 5;
    int wr = w & 3, wc = w >> 2;
    wmma::fragment<wmma::accumulator, 16, 16, 16, float> acc;
    wmma::fill_fragment(acc, 0.f);

#pragma unroll
    for (int k = 0; k < 8; k++) {
        wmma::fragment<wmma::matrix_a, 16, 16, 16, __half, wmma::row_major> a;
        wmma::fragment<wmma::matrix_b, 16, 16, 16, __half, wmma::row_major> b;
        wmma::load_matrix_sync(a, As + (wr * 16) * LDA + k * 16, LDA);
        wmma::load_matrix_sync(b, Bs + (k * 16) * LDB2 + wc * 16, LDB2);
        wmma::mma_sync(acc, a, b, acc);
    }

    __syncthreads();
    wmma::store_matrix_sync(outs + (wr * 16) * 32 + wc * 16, acc, 32, wmma::mem_row_major);
    __syncthreads();

    for (int i = tid; i < 64 * 16; i += 256) {
        int r = i >> 4, c2 = i & 15;
        int g = row0 + r;
        if (g < N) {
            float2 f = ((const float2*)outs)[r * 16 + c2];
            ((half2*)g_h2h)[(size_t)g * 16 + c2] = __floats2half2_rn(f.x, f.y);
        }
    }

    float asv = att_s[lane];
    float adv = att_d[lane];
#pragma unroll
    for (int r8 = 0; r8 < 8; r8++) {
        int r = w * 8 + r8;
        int g = row0 + r;
        float hv = outs[r * 32 + lane];
        float ps = hv * asv;
        float pd = hv * adv;
#pragma unroll
        for (int o = 16; o > 0; o >>= 1) {
            ps += __shfl_xor_sync(0xFFFFFFFFu, ps, o);
            pd += __shfl_xor_sync(0xFFFFFFFFu, pd, o);
        }
        if (lane == 0 && g < N) {
            g_asrc2[g] = ps;
            g_adst2[g] = pd;
        }
    }
}

// ---------------- layer-1 aggregation (writes fp16 h1') -----------------------
__global__ void agg1_kernel(const float* __restrict__ b1, int N, int EN) {
    int n = (blockIdx.x * blockDim.x + threadIdx.x) >> 5;
    int lane = threadIdx.x & 31;
    if (n >= N) return;
    if (lane == 0) g_cursor[n] = 0;     // self-heal
    int h = lane >> 3;
    float ad = g_adst1[n * 4 + h];
    int beg = g_rowfin[n];
    int end = (n + 1 < N) ? g_rowfin[n + 1] : EN;
    const uint2* hb = (const uint2*)g_h1h;

    float4 acc = make_float4(0.f, 0.f, 0.f, 0.f);
    float den = 0.f;

    for (int base = beg; base < end; base += 32) {
        int m = end - base; if (m > 32) m = 32;
        int sv = (base + lane < end) ? g_esrc[base + lane] : 0;
        int j = 0;
        for (; j + 4 <= m; j += 4) {
            int s0 = __shfl_sync(0xFFFFFFFFu, sv, j);
            int s1 = __shfl_sync(0xFFFFFFFFu, sv, j + 1);
            int s2 = __shfl_sync(0xFFFFFFFFu, sv, j + 2);
            int s3 = __shfl_sync(0xFFFFFFFFu, sv, j + 3);
            float e0 = g_asrc1[s0 * 4 + h] + ad;
            float e1 = g_asrc1[s1 * 4 + h] + ad;
            float e2 = g_asrc1[s2 * 4 + h] + ad;
            float e3 = g_asrc1[s3 * 4 + h] + ad;
            uint2 r0 = hb[s0 * 32 + lane];
            uint2 r1 = hb[s1 * 32 + lane];
            uint2 r2 = hb[s2 * 32 + lane];
            uint2 r3 = hb[s3 * 32 + lane];
            e0 = (e0 > 0.f) ? e0 : NEG_SLOPE * e0;
            e1 = (e1 > 0.f) ? e1 : NEG_SLOPE * e1;
            e2 = (e2 > 0.f) ? e2 : NEG_SLOPE * e2;
            e3 = (e3 > 0.f) ? e3 : NEG_SLOPE * e3;
            float x0 = __expf(e0), x1 = __expf(e1);
            float x2 = __expf(e2), x3 = __expf(e3);
            den += x0 + x1 + x2 + x3;
            float2 a0 = __half22float2(*(half2*)&r0.x);
            float2 a1 = __half22float2(*(half2*)&r0.y);
            float2 c0 = __half22float2(*(half2*)&r1.x);
            float2 c1 = __half22float2(*(half2*)&r1.y);
            float2 d0 = __half22float2(*(half2*)&r2.x);
            float2 d1 = __half22float2(*(half2*)&r2.y);
            float2 f0 = __half22float2(*(half2*)&r3.x);
            float2 f1 = __half22float2(*(half2*)&r3.y);
            acc.x += x0 * a0.x + x1 * c0.x + x2 * d0.x + x3 * f0.x;
            acc.y += x0 * a0.y + x1 * c0.y + x2 * d0.y + x3 * f0.y;
            acc.z += x0 * a1.x + x1 * c1.x + x2 * d1.x + x3 * f1.x;
            acc.w += x0 * a1.y + x1 * c1.y + x2 * d1.y + x3 * f1.y;
        }
        for (; j < m; j++) {
            int s = __shfl_sync(0xFFFFFFFFu, sv, j);
            float e = g_asrc1[s * 4 + h] + ad;
            e = (e > 0.f) ? e : NEG_SLOPE * e;
            float ex = __expf(e);
            uint2 r0 = hb[s * 32 + lane];
            float2 a0 = __half22float2(*(half2*)&r0.x);
            float2 a1 = __half22float2(*(half2*)&r0.y);
            den += ex;
            acc.x += ex * a0.x; acc.y += ex * a0.y;
            acc.z += ex * a1.x; acc.w += ex * a1.y;
        }
    }
    float inv = 1.f / (den + EPS);
    float4 bias = ((const float4*)b1)[lane];
    float rx = fmaxf(acc.x * inv + bias.x, 0.f);
    float ry = fmaxf(acc.y * inv + bias.y, 0.f);
    float rz = fmaxf(acc.z * inv + bias.z, 0.f);
    float rw = fmaxf(acc.w * inv + bias.w, 0.f);
    half2 h0 = __floats2half2_rn(rx, ry);
    half2 h1 = __floats2half2_rn(rz, rw);
    uint2 p;
    p.x = *(uint32_t*)&h0;
    p.y = *(uint32_t*)&h1;
    ((uint2*)g_agg1h)[n * 32 + lane] = p;
}

// ---------------- layer-2 aggregation ------------------------------------------
__global__ void agg2_kernel(float* __restrict__ out,
                            const float* __restrict__ b2, int N, int EN) {
    int n = (blockIdx.x * blockDim.x + threadIdx.x) >> 5;
    int lane = threadIdx.x & 31;
    if (n >= N) return;
    float ad = g_adst2[n];
    int beg = g_rowfin[n];
    int end = (n + 1 < N) ? g_rowfin[n + 1] : EN;

    float acc = 0.f;
    float den = 0.f;
    for (int base = beg; base < end; base += 32) {
        int m = end - base; if (m > 32) m = 32;
        int sv = 0; float av = 0.f;
        if (base + lane < end) {
            sv = g_esrc[base + lane];
            av = g_asrc2[sv];
        }
        int j = 0;
        for (; j + 4 <= m; j += 4) {
            int s0 = __shfl_sync(0xFFFFFFFFu, sv, j);
            int s1 = __shfl_sync(0xFFFFFFFFu, sv, j + 1);
            int s2 = __shfl_sync(0xFFFFFFFFu, sv, j + 2);
            int s3 = __shfl_sync(0xFFFFFFFFu, sv, j + 3);
            float e0 = __shfl_sync(0xFFFFFFFFu, av, j) + ad;
            float e1 = __shfl_sync(0xFFFFFFFFu, av, j + 1) + ad;
            float e2 = __shfl_sync(0xFFFFFFFFu, av, j + 2) + ad;
            float e3 = __shfl_sync(0xFFFFFFFFu, av, j + 3) + ad;
            float v0 = __half2float(g_h2h[s0 * 32 + lane]);
            float v1 = __half2float(g_h2h[s1 * 32 + lane]);
            float v2 = __half2float(g_h2h[s2 * 32 + lane]);
            float v3 = __half2float(g_h2h[s3 * 32 + lane]);
            e0 = (e0 > 0.f) ? e0 : NEG_SLOPE * e0;
            e1 = (e1 > 0.f) ? e1 : NEG_SLOPE * e1;
            e2 = (e2 > 0.f) ? e2 : NEG_SLOPE * e2;
            e3 = (e3 > 0.f) ? e3 : NEG_SLOPE * e3;
            float x0 = __expf(e0), x1 = __expf(e1);
            float x2 = __expf(e2), x3 = __expf(e3);
            den += x0 + x1 + x2 + x3;
            acc += x0 * v0 + x1 * v1 + x2 * v2 + x3 * v3;
        }
        for (; j < m; j++) {
            int s = __shfl_sync(0xFFFFFFFFu, sv, j);
            float e = __shfl_sync(0xFFFFFFFFu, av, j) + ad;
            e = (e > 0.f) ? e : NEG_SLOPE * e;
            float ex = __expf(e);
            den += ex;
            acc += ex * __half2float(g_h2h[s * 32 + lane]);
        }
    }
    out[n * 32 + lane] = acc / (den + EPS) + b2[lane];
}

// ---------------- launch ------------------------------------------------------
extern "C" void kernel_launch(void* const* d_in, const int* in_sizes, int n_in,
                              void* d_out, int out_size) {
    const float* x      = (const float*)d_in[0];
    const int*   ei     = (const int*)  d_in[1];
    const float* W1     = (const float*)d_in[2];
    const float* att_s1 = (const float*)d_in[3];
    const float* att_d1 = (const float*)d_in[4];
    const float* b1     = (const float*)d_in[5];
    const float* W2     = (const float*)d_in[6];
    const float* att_s2 = (const float*)d_in[7];
    const float* att_d2 = (const float*)d_in[8];
    const float* b2     = (const float*)d_in[9];

    int N = in_sizes[0] / IN_DIM;
    int E = in_sizes[1] / 2;
    const int* src = ei;
    const int* dst = ei + E;
    float* out = (float*)d_out;
    int EN = E + N;
    int NB = (N + 1023) / 1024;

    static bool init_done = false;
    static cudaStream_t s2;
    static cudaEvent_t evFork, evJoin;
    if (!init_done) {
        cudaFuncSetAttribute(gemm1_kernel, cudaFuncAttributeMaxDynamicSharedMemorySize, GEMM1_SMEM);
        cudaFuncSetAttribute(gemm2_kernel, cudaFuncAttributeMaxDynamicSharedMemorySize, GEMM2_SMEM);
        cudaStreamCreateWithFlags(&s2, cudaStreamNonBlocking);
        cudaEventCreateWithFlags(&evFork, cudaEventDisableTiming);
        cudaEventCreateWithFlags(&evJoin, cudaEventDisableTiming);
        init_done = true;
    }

    // ---- fork: CSR chain on s2 ∥ dense chain on main ----
    cudaEventRecord(evFork, 0);
    cudaStreamWaitEvent(s2, evFork, 0);

    hist_kernel<<<(EN + 255) / 256, 256, 0, s2>>>(dst, E, EN);
    scan1_kernel<<<NB, 1024, 0, s2>>>(N);
    scatter_kernel<<<(EN + 255) / 256, 256, 0, s2>>>(src, dst, E, EN);
    cudaEventRecord(evJoin, s2);

    conv_kernel<<<592, 256>>>(x, W1, W2, N);
    gemm1_kernel<<<(N + 63) / 64, 256, GEMM1_SMEM>>>(att_s1, att_d1, N);

    // ---- join ----
    cudaStreamWaitEvent(0, evJoin, 0);

    agg1_kernel<<<(N * 32 + 255) / 256, 256>>>(b1, N, EN);
    gemm2_kernel<<<(N + 63) / 64, 256, GEMM2_SMEM>>>(att_s2, att_d2, N);
    agg2_kernel<<<(N * 32 + 255) / 256, 256>>>(out, b2, N, EN);
}